// round 1
// baseline (speedup 1.0000x reference)
#include <cuda_runtime.h>
#include <cstdint>

// Problem constants
#define B_     64
#define H_     512
#define W_     512
#define C_     3
#define G_     64
#define K_     3
#define D_IN   (K_*G_*G_*C_)   // 36864
#define HG_    128
#define HL_    128

// GEMM split-K config
#define NCHUNK 288
#define DC     128             // D per chunk (NCHUNK*DC == D_IN)
#define TD     16              // smem d-tile

// Scratch (device globals; no runtime allocation allowed)
__device__ float g_phi[(size_t)B_ * D_IN];            // 9.4 MB
__device__ float g_part[(size_t)NCHUNK * B_ * HG_];   // 9.4 MB

// ---------------------------------------------------------------------------
// Kernel 1: glimpse extraction + avg pooling
// grid (gy=64, k=3, b=64), 256 threads.
// Stages f source rows (contiguous 64f px * 3ch each) into smem coalesced,
// then 192 threads pool f x f blocks and write phi coalesced.
// ---------------------------------------------------------------------------
__global__ __launch_bounds__(256) void extract_kernel(
    const float* __restrict__ x, const float* __restrict__ l)
{
    __shared__ float buf[4 * 64 * 4 * 3];   // max f=4: 4 rows * 768 floats = 12KB

    const int gy = blockIdx.x;
    const int k  = blockIdx.y;
    const int b  = blockIdx.z;
    const int f    = 1 << k;          // 1, 2, 4
    const int size = G_ * f;          // 64, 128, 256
    const int rowlen = size * 3;      // floats per source row segment
    const int tid = threadIdx.x;

    // denormalize coords exactly like reference: trunc((0.5*(l+1))*512)
    const float lx = l[b * 2 + 0];
    const float ly = l[b * 2 + 1];
    const int cx = (int)((0.5f * (lx + 1.0f)) * 512.0f);
    const int cy = (int)((0.5f * (ly + 1.0f)) * 512.0f);
    const int ys = cy - size / 2;
    const int xs = cx - size / 2;

    // stage f source rows, zero-filled outside [0,512)
    const int total = f * rowlen;
    for (int idx = tid; idx < total; idx += 256) {
        const int r = idx / rowlen;
        const int j = idx - r * rowlen;
        const int y = ys + gy * f + r;
        const int col = xs + j / 3;
        float v = 0.0f;
        if (y >= 0 && y < H_ && col >= 0 && col < W_) {
            const int ch = j - (j / 3) * 3;
            v = x[(((size_t)b * H_ + y) * W_ + col) * C_ + ch];
        }
        buf[r * rowlen + j] = v;
    }
    __syncthreads();

    // pool: 64 gx * 3 c outputs
    if (tid < G_ * C_) {
        const int gx = tid / 3;
        const int c  = tid - gx * 3;
        float s = 0.0f;
        #pragma unroll 4
        for (int dy = 0; dy < f; dy++)
            for (int dx = 0; dx < f; dx++)
                s += buf[dy * rowlen + (gx * f + dx) * 3 + c];
        const int d = ((k * G_ + gy) * G_ + gx) * C_ + c;
        g_phi[(size_t)b * D_IN + d] = s / (float)(f * f);
    }
}

// ---------------------------------------------------------------------------
// Kernel 2: split-K fp32 GEMM  phi(64 x 36864) @ W1(36864 x 128)
// grid NCHUNK blocks, 256 threads. Each block owns DC K-dims, produces a full
// 64x128 partial tile (thread = 4 rows x 8 cols), written to g_part.
// ---------------------------------------------------------------------------
__global__ __launch_bounds__(256) void gemm_kernel(const float* __restrict__ W1)
{
    __shared__ float sPhi[TD][B_];        // [d][b]
    __shared__ float sW[TD][HG_];         // [d][n]

    const int chunk = blockIdx.x;
    const int d0 = chunk * DC;
    const int tid = threadIdx.x;
    const int tm = tid >> 4;      // 0..15  -> rows 4*tm..4*tm+3
    const int tn = tid & 15;      // 0..15  -> cols 8*tn..8*tn+7

    float acc[4][8];
    #pragma unroll
    for (int i = 0; i < 4; i++)
        #pragma unroll
        for (int j = 0; j < 8; j++) acc[i][j] = 0.0f;

    for (int t = 0; t < DC; t += TD) {
        // load phi tile (16 d x 64 b)
        #pragma unroll
        for (int i = 0; i < 4; i++) {
            const int idx = tid + i * 256;
            const int bb = idx >> 4;
            const int dd = idx & 15;
            sPhi[dd][bb] = g_phi[(size_t)bb * D_IN + d0 + t + dd];
        }
        // load W1 tile (16 d x 128 n), coalesced
        #pragma unroll
        for (int i = 0; i < 8; i++) {
            const int idx = tid + i * 256;
            const int dd = idx >> 7;
            const int n  = idx & 127;
            sW[dd][n] = W1[(size_t)(d0 + t + dd) * HG_ + n];
        }
        __syncthreads();

        #pragma unroll
        for (int dd = 0; dd < TD; dd++) {
            float pv[4], wv[8];
            const float4 p4 = *reinterpret_cast<const float4*>(&sPhi[dd][tm * 4]);
            pv[0] = p4.x; pv[1] = p4.y; pv[2] = p4.z; pv[3] = p4.w;
            const float4 w4a = *reinterpret_cast<const float4*>(&sW[dd][tn * 8]);
            const float4 w4b = *reinterpret_cast<const float4*>(&sW[dd][tn * 8 + 4]);
            wv[0]=w4a.x; wv[1]=w4a.y; wv[2]=w4a.z; wv[3]=w4a.w;
            wv[4]=w4b.x; wv[5]=w4b.y; wv[6]=w4b.z; wv[7]=w4b.w;
            #pragma unroll
            for (int i = 0; i < 4; i++)
                #pragma unroll
                for (int j = 0; j < 8; j++)
                    acc[i][j] += pv[i] * wv[j];
        }
        __syncthreads();
    }

    // write partials
    float* part = &g_part[(size_t)chunk * B_ * HG_];
    #pragma unroll
    for (int i = 0; i < 4; i++) {
        const int row = tm * 4 + i;
        #pragma unroll
        for (int j = 0; j < 8; j++)
            part[row * HG_ + tn * 8 + j] = acc[i][j];
    }
}

// ---------------------------------------------------------------------------
// Kernel 3: reduce partials + bias + relu, and the l-branch (l @ W2), concat.
// grid 64 (one block per batch), 512 threads: h = tid&127, p = tid>>7.
// ---------------------------------------------------------------------------
__global__ __launch_bounds__(512) void finalize_kernel(
    const float* __restrict__ l, const float* __restrict__ b1,
    const float* __restrict__ W2, const float* __restrict__ b2,
    float* __restrict__ out)
{
    __shared__ float red[4][HG_];
    const int b = blockIdx.x;
    const int tid = threadIdx.x;
    const int h = tid & 127;
    const int p = tid >> 7;

    float s = 0.0f;
    #pragma unroll 8
    for (int c = p; c < NCHUNK; c += 4)
        s += g_part[(size_t)c * (B_ * HG_) + b * HG_ + h];
    red[p][h] = s;
    __syncthreads();

    if (p == 0) {
        const float v = red[0][h] + red[1][h] + red[2][h] + red[3][h] + b1[h];
        out[b * (HG_ + HL_) + h] = fmaxf(v, 0.0f);
        const float lw = l[b * 2 + 0] * W2[h] + l[b * 2 + 1] * W2[HL_ + h] + b2[h];
        out[b * (HG_ + HL_) + HG_ + h] = fmaxf(lw, 0.0f);
    }
}

// ---------------------------------------------------------------------------
extern "C" void kernel_launch(void* const* d_in, const int* in_sizes, int n_in,
                              void* d_out, int out_size)
{
    const float* x  = (const float*)d_in[0];
    const float* l  = (const float*)d_in[1];
    const float* W1 = (const float*)d_in[2];
    const float* b1 = (const float*)d_in[3];
    const float* W2 = (const float*)d_in[4];
    const float* b2 = (const float*)d_in[5];
    float* out = (float*)d_out;

    dim3 eg(G_, K_, B_);
    extract_kernel<<<eg, 256>>>(x, l);
    gemm_kernel<<<NCHUNK, 256>>>(W1);
    finalize_kernel<<<B_, 512>>>(l, b1, W2, b2, out);
}

// round 2
// speedup vs baseline: 1.4749x; 1.4749x over previous
#include <cuda_runtime.h>
#include <cstdint>

// Problem constants
#define B_     64
#define H_     512
#define W_     512
#define C_     3
#define G_     64
#define K_     3
#define D_IN   (K_*G_*G_*C_)   // 36864
#define HG_    128
#define HL_    128

// GEMM split-K config
#define NCHUNK 288
#define DC     128             // D per chunk (NCHUNK*DC == D_IN)
#define TD     16              // smem d-tile

// Scratch (device globals; no runtime allocation allowed)
__device__ float g_phi[(size_t)B_ * D_IN];            // 9.4 MB
__device__ float g_part[(size_t)NCHUNK * B_ * HG_];   // 9.4 MB

// ---------------------------------------------------------------------------
// Kernel 1: glimpse extraction + avg pooling (v2 — issue-lean)
//
// Grid: x = 112 flattened (k=0: 16 blocks x 4 out-rows, k=1: 32 x 2,
//       k=2: 64 x 1), y = batch. 192 threads.
// Every block stages exactly 4 contiguous source rows. A source row segment
// [col][ch] is contiguous in x and identical to the smem layout, so staging
// is a straight predicated copy: no div/mod anywhere in the hot path.
// ---------------------------------------------------------------------------
template<int KK>
__device__ __forceinline__ void extract_impl(
    const float* __restrict__ x, const float* __restrict__ l,
    float* __restrict__ buf, int gy0, int b, int tid)
{
    constexpr int f      = 1 << KK;       // 1, 2, 4
    constexpr int r      = 4 >> KK;       // out-rows per block: 4, 2, 1
    constexpr int size   = G_ * f;        // 64, 128, 256
    constexpr int rowlen = size * 3;      // 192, 384, 768 floats

    // denormalize coords exactly like reference: trunc((0.5*(l+1))*512)
    const float lx = __ldg(&l[b * 2 + 0]);
    const float ly = __ldg(&l[b * 2 + 1]);
    const int cx = (int)((0.5f * (lx + 1.0f)) * 512.0f);
    const int cy = (int)((0.5f * (ly + 1.0f)) * 512.0f);
    const int xs = cx - size / 2;
    const int ys = cy - size / 2 + gy0 * f;

    const int jlo = (xs < 0 ? -xs : 0) * 3;
    const int xe  = xs + size;
    const int jhi = ((xe > W_ ? W_ : xe) - xs) * 3;   // may be <= jlo (all OOB)

    // stage 4 contiguous source rows
    #pragma unroll
    for (int rr = 0; rr < 4; rr++) {
        const int y = ys + rr;
        const bool yok = (y >= 0) && (y < H_);
        const float* rowp = x + (((size_t)b * H_ + y) * W_ + xs) * C_;
        #pragma unroll
        for (int it = 0; it < (rowlen + 191) / 192; it++) {
            const int j = tid + it * 192;
            float v = 0.0f;
            if (yok && j >= jlo && j < jhi) v = __ldg(rowp + j);
            buf[rr * rowlen + j] = v;
        }
    }
    __syncthreads();

    // pooling: thread tid = gx*3 + c produces r outputs
    const int gx = tid / 3;            // computed once, not in hot loop
    const int c  = tid - gx * 3;
    constexpr float inv = 1.0f / (float)(f * f);

    #pragma unroll
    for (int orow = 0; orow < r; orow++) {
        float s = 0.0f;
        #pragma unroll
        for (int dy = 0; dy < f; dy++)
            #pragma unroll
            for (int dx = 0; dx < f; dx++)
                s += buf[(orow * f + dy) * rowlen + (gx * f + dx) * 3 + c];
        // d = ((KK*64 + gy0+orow)*64 + gx)*3 + c = (KK*64 + gy0+orow)*192 + tid
        g_phi[(size_t)b * D_IN + (KK * G_ + gy0 + orow) * (G_ * C_) + tid] = s * inv;
    }
}

__global__ __launch_bounds__(192) void extract_kernel(
    const float* __restrict__ x, const float* __restrict__ l)
{
    __shared__ float buf[4 * 768];     // 12 KB, max rowlen (k=2) x 4 rows

    const int bx  = blockIdx.x;        // 0..111
    const int b   = blockIdx.y;
    const int tid = threadIdx.x;

    if (bx < 16) {
        extract_impl<0>(x, l, buf, bx * 4, b, tid);
    } else if (bx < 48) {
        extract_impl<1>(x, l, buf, (bx - 16) * 2, b, tid);
    } else {
        extract_impl<2>(x, l, buf, bx - 48, b, tid);
    }
}

// ---------------------------------------------------------------------------
// Kernel 2: split-K fp32 GEMM  phi(64 x 36864) @ W1(36864 x 128)
// grid NCHUNK blocks, 256 threads. Each block owns DC K-dims, produces a full
// 64x128 partial tile (thread = 4 rows x 8 cols), written to g_part.
// ---------------------------------------------------------------------------
__global__ __launch_bounds__(256) void gemm_kernel(const float* __restrict__ W1)
{
    __shared__ float sPhi[TD][B_];        // [d][b]
    __shared__ float sW[TD][HG_];         // [d][n]

    const int chunk = blockIdx.x;
    const int d0 = chunk * DC;
    const int tid = threadIdx.x;
    const int tm = tid >> 4;      // 0..15  -> rows 4*tm..4*tm+3
    const int tn = tid & 15;      // 0..15  -> cols 8*tn..8*tn+7

    float acc[4][8];
    #pragma unroll
    for (int i = 0; i < 4; i++)
        #pragma unroll
        for (int j = 0; j < 8; j++) acc[i][j] = 0.0f;

    for (int t = 0; t < DC; t += TD) {
        // load phi tile (16 d x 64 b)
        #pragma unroll
        for (int i = 0; i < 4; i++) {
            const int idx = tid + i * 256;
            const int bb = idx >> 4;
            const int dd = idx & 15;
            sPhi[dd][bb] = g_phi[(size_t)bb * D_IN + d0 + t + dd];
        }
        // load W1 tile (16 d x 128 n), coalesced
        #pragma unroll
        for (int i = 0; i < 8; i++) {
            const int idx = tid + i * 256;
            const int dd = idx >> 7;
            const int n  = idx & 127;
            sW[dd][n] = W1[(size_t)(d0 + t + dd) * HG_ + n];
        }
        __syncthreads();

        #pragma unroll
        for (int dd = 0; dd < TD; dd++) {
            float pv[4], wv[8];
            const float4 p4 = *reinterpret_cast<const float4*>(&sPhi[dd][tm * 4]);
            pv[0] = p4.x; pv[1] = p4.y; pv[2] = p4.z; pv[3] = p4.w;
            const float4 w4a = *reinterpret_cast<const float4*>(&sW[dd][tn * 8]);
            const float4 w4b = *reinterpret_cast<const float4*>(&sW[dd][tn * 8 + 4]);
            wv[0]=w4a.x; wv[1]=w4a.y; wv[2]=w4a.z; wv[3]=w4a.w;
            wv[4]=w4b.x; wv[5]=w4b.y; wv[6]=w4b.z; wv[7]=w4b.w;
            #pragma unroll
            for (int i = 0; i < 4; i++)
                #pragma unroll
                for (int j = 0; j < 8; j++)
                    acc[i][j] += pv[i] * wv[j];
        }
        __syncthreads();
    }

    // write partials
    float* part = &g_part[(size_t)chunk * B_ * HG_];
    #pragma unroll
    for (int i = 0; i < 4; i++) {
        const int row = tm * 4 + i;
        #pragma unroll
        for (int j = 0; j < 8; j++)
            part[row * HG_ + tn * 8 + j] = acc[i][j];
    }
}

// ---------------------------------------------------------------------------
// Kernel 3: reduce partials + bias + relu, and the l-branch (l @ W2), concat.
// grid 64 (one block per batch), 512 threads: h = tid&127, p = tid>>7.
// ---------------------------------------------------------------------------
__global__ __launch_bounds__(512) void finalize_kernel(
    const float* __restrict__ l, const float* __restrict__ b1,
    const float* __restrict__ W2, const float* __restrict__ b2,
    float* __restrict__ out)
{
    __shared__ float red[4][HG_];
    const int b = blockIdx.x;
    const int tid = threadIdx.x;
    const int h = tid & 127;
    const int p = tid >> 7;

    float s = 0.0f;
    #pragma unroll 8
    for (int c = p; c < NCHUNK; c += 4)
        s += g_part[(size_t)c * (B_ * HG_) + b * HG_ + h];
    red[p][h] = s;
    __syncthreads();

    if (p == 0) {
        const float v = red[0][h] + red[1][h] + red[2][h] + red[3][h] + b1[h];
        out[b * (HG_ + HL_) + h] = fmaxf(v, 0.0f);
        const float lw = l[b * 2 + 0] * W2[h] + l[b * 2 + 1] * W2[HL_ + h] + b2[h];
        out[b * (HG_ + HL_) + HG_ + h] = fmaxf(lw, 0.0f);
    }
}

// ---------------------------------------------------------------------------
extern "C" void kernel_launch(void* const* d_in, const int* in_sizes, int n_in,
                              void* d_out, int out_size)
{
    const float* x  = (const float*)d_in[0];
    const float* l  = (const float*)d_in[1];
    const float* W1 = (const float*)d_in[2];
    const float* b1 = (const float*)d_in[3];
    const float* W2 = (const float*)d_in[4];
    const float* b2 = (const float*)d_in[5];
    float* out = (float*)d_out;

    dim3 eg(112, B_);
    extract_kernel<<<eg, 192>>>(x, l);
    gemm_kernel<<<NCHUNK, 256>>>(W1);
    finalize_kernel<<<B_, 512>>>(l, b1, W2, b2, out);
}

// round 4
// speedup vs baseline: 1.8581x; 1.2598x over previous
#include <cuda_runtime.h>
#include <cuda_bf16.h>
#include <cstdint>

// Problem constants
#define B_     64
#define H_     512
#define W_     512
#define C_     3
#define G_     64
#define K_     3
#define D_IN   (K_*G_*G_*C_)   // 36864
#define HG_    128
#define HL_    128

// GEMM split-K config
#define NCHUNK 288
#define DC     128             // K-dims per CTA chunk (NCHUNK*DC == D_IN)

// Scratch (device globals; no runtime allocation allowed)
__device__ float g_phi[(size_t)B_ * D_IN];            // 9.4 MB
__device__ float g_part[(size_t)NCHUNK * B_ * HG_];   // 9.4 MB

__device__ __forceinline__ uint32_t smem_u32(const void* p) {
    uint32_t a;
    asm("{ .reg .u64 t; cvta.to.shared.u64 t, %1; cvt.u32.u64 %0, t; }"
        : "=r"(a) : "l"(p));
    return a;
}

// ---------------------------------------------------------------------------
// Kernel 1: glimpse extraction + avg pooling (unchanged from R2: 15.5us)
// ---------------------------------------------------------------------------
template<int KK>
__device__ __forceinline__ void extract_impl(
    const float* __restrict__ x, const float* __restrict__ l,
    float* __restrict__ buf, int gy0, int b, int tid)
{
    constexpr int f      = 1 << KK;
    constexpr int r      = 4 >> KK;
    constexpr int size   = G_ * f;
    constexpr int rowlen = size * 3;

    const float lx = __ldg(&l[b * 2 + 0]);
    const float ly = __ldg(&l[b * 2 + 1]);
    const int cx = (int)((0.5f * (lx + 1.0f)) * 512.0f);
    const int cy = (int)((0.5f * (ly + 1.0f)) * 512.0f);
    const int xs = cx - size / 2;
    const int ys = cy - size / 2 + gy0 * f;

    const int jlo = (xs < 0 ? -xs : 0) * 3;
    const int xe  = xs + size;
    const int jhi = ((xe > W_ ? W_ : xe) - xs) * 3;

    #pragma unroll
    for (int rr = 0; rr < 4; rr++) {
        const int y = ys + rr;
        const bool yok = (y >= 0) && (y < H_);
        const float* rowp = x + (((size_t)b * H_ + y) * W_ + xs) * C_;
        #pragma unroll
        for (int it = 0; it < (rowlen + 191) / 192; it++) {
            const int j = tid + it * 192;
            float v = 0.0f;
            if (yok && j >= jlo && j < jhi) v = __ldg(rowp + j);
            buf[rr * rowlen + j] = v;
        }
    }
    __syncthreads();

    const int gx = tid / 3;
    const int c  = tid - gx * 3;
    constexpr float inv = 1.0f / (float)(f * f);

    #pragma unroll
    for (int orow = 0; orow < r; orow++) {
        float s = 0.0f;
        #pragma unroll
        for (int dy = 0; dy < f; dy++)
            #pragma unroll
            for (int dx = 0; dx < f; dx++)
                s += buf[(orow * f + dy) * rowlen + (gx * f + dx) * 3 + c];
        g_phi[(size_t)b * D_IN + (KK * G_ + gy0 + orow) * (G_ * C_) + tid] = s * inv;
    }
}

__global__ __launch_bounds__(192) void extract_kernel(
    const float* __restrict__ x, const float* __restrict__ l)
{
    __shared__ float buf[4 * 768];
    const int bx  = blockIdx.x;
    const int b   = blockIdx.y;
    const int tid = threadIdx.x;

    if (bx < 16)       extract_impl<0>(x, l, buf, bx * 4, b, tid);
    else if (bx < 48)  extract_impl<1>(x, l, buf, (bx - 16) * 2, b, tid);
    else               extract_impl<2>(x, l, buf, bx - 48, b, tid);
}

// ---------------------------------------------------------------------------
// Kernel 2: split-K GEMM via mma.sync bf16 (portable HMMA), bf16x3 split for
// fp32-grade accuracy: D = Ah*Bh + Ah*Bl + Al*Bh, fp32 accumulate.
// Grid NCHUNK=288, 256 threads (8 warps = 4 m-tiles x 2 n-halves).
// A: phi slice 64x128; B: W1 slice transposed to [n][k] 128x128.
// ---------------------------------------------------------------------------
#define KSTR   136                       // padded K stride in bf16 (272B rows)
#define A_TILE (64 * KSTR * 2)           // 17408 B
#define B_TILE (128 * KSTR * 2)          // 34816 B
#define OFF_AH 0
#define OFF_AL A_TILE
#define OFF_BH (2 * A_TILE)
#define OFF_BL (2 * A_TILE + B_TILE)
#define SMEM_GEMM (2 * A_TILE + 2 * B_TILE)   // 104448 B

__device__ __forceinline__ void ldsm_x4(uint32_t a[4], uint32_t addr) {
    asm volatile("ldmatrix.sync.aligned.m8n8.x4.shared.b16 {%0,%1,%2,%3}, [%4];"
                 : "=r"(a[0]), "=r"(a[1]), "=r"(a[2]), "=r"(a[3]) : "r"(addr));
}
__device__ __forceinline__ void ldsm_x2(uint32_t b[2], uint32_t addr) {
    asm volatile("ldmatrix.sync.aligned.m8n8.x2.shared.b16 {%0,%1}, [%2];"
                 : "=r"(b[0]), "=r"(b[1]) : "r"(addr));
}
__device__ __forceinline__ void mma_bf16(
    float c[4], const uint32_t a[4], const uint32_t b[2])
{
    asm volatile(
        "mma.sync.aligned.m16n8k16.row.col.f32.bf16.bf16.f32 "
        "{%0,%1,%2,%3}, {%4,%5,%6,%7}, {%8,%9}, {%0,%1,%2,%3};"
        : "+f"(c[0]), "+f"(c[1]), "+f"(c[2]), "+f"(c[3])
        : "r"(a[0]), "r"(a[1]), "r"(a[2]), "r"(a[3]), "r"(b[0]), "r"(b[1]));
}

__device__ __forceinline__ uint32_t hi_lo_pack(float v0, float v1, uint32_t& lo_out)
{
    __nv_bfloat16 h0 = __float2bfloat16(v0);
    __nv_bfloat16 h1 = __float2bfloat16(v1);
    __nv_bfloat16 e0 = __float2bfloat16(v0 - __bfloat162float(h0));
    __nv_bfloat16 e1 = __float2bfloat16(v1 - __bfloat162float(h1));
    __nv_bfloat162 hp; hp.x = h0; hp.y = h1;
    __nv_bfloat162 lp; lp.x = e0; lp.y = e1;
    lo_out = *reinterpret_cast<uint32_t*>(&lp);
    return *reinterpret_cast<uint32_t*>(&hp);
}

__global__ __launch_bounds__(256) void gemm_mma_kernel(const float* __restrict__ W1)
{
    extern __shared__ char smem[];
    const uint32_t sb = smem_u32(smem);
    const int tid  = threadIdx.x;
    const int wid  = tid >> 5;
    const int lane = tid & 31;
    const int d0   = blockIdx.x * DC;

    // ---- fill A (phi 64 x 128) hi/lo, rows m, padded stride KSTR ----
    for (int idx = tid; idx < 64 * 64; idx += 256) {
        const int m  = idx >> 6;
        const int kp = idx & 63;                     // k pair: k = 2*kp
        const float2 p = *reinterpret_cast<const float2*>(
            &g_phi[(size_t)m * D_IN + d0 + 2 * kp]);
        uint32_t lo, hi = hi_lo_pack(p.x, p.y, lo);
        const int off = m * (KSTR * 2) + kp * 4;     // bytes
        *reinterpret_cast<uint32_t*>(smem + OFF_AH + off) = hi;
        *reinterpret_cast<uint32_t*>(smem + OFF_AL + off) = lo;
    }

    // ---- fill B^T (128 n-rows x 128 k) hi/lo: B[n][k] = W1[d0+k][n] ----
    for (int idx = tid; idx < 64 * 128; idx += 256) {
        const int kk = idx >> 7;                     // k pair
        const int n  = idx & 127;                    // coalesced over W1 rows
        const float v0 = __ldg(&W1[(size_t)(d0 + 2 * kk)     * HG_ + n]);
        const float v1 = __ldg(&W1[(size_t)(d0 + 2 * kk + 1) * HG_ + n]);
        uint32_t lo, hi = hi_lo_pack(v0, v1, lo);
        const int off = n * (KSTR * 2) + kk * 4;
        *reinterpret_cast<uint32_t*>(smem + OFF_BH + off) = hi;
        *reinterpret_cast<uint32_t*>(smem + OFF_BL + off) = lo;
    }
    __syncthreads();

    // ---- warp tiling: mt = wid>>1 (m16), nh = wid&1 (n64 = 8 n-tiles) ----
    const int mt = wid >> 1;
    const int nh = wid & 1;

    // ldmatrix address offsets (bytes, relative to tile base)
    const uint32_t aRel = (uint32_t)((mt * 16 + (lane & 15)) * (KSTR * 2)
                                     + (lane >> 4) * 16);
    const uint32_t bRel = (uint32_t)((nh * 64 + (lane & 7)) * (KSTR * 2)
                                     + ((lane >> 3) & 3 & 1) * 16
                                     + ((lane >> 3) & 1) * 0);  // see below
    // lanes 0-15 feed x2; give lanes 16-31 harmless duplicates:
    const uint32_t bRelFix = (uint32_t)((nh * 64 + (lane & 7)) * (KSTR * 2)
                                        + ((lane >> 3) & 1) * 16);

    float acc[8][4];
    #pragma unroll
    for (int nt = 0; nt < 8; nt++)
        #pragma unroll
        for (int j = 0; j < 4; j++) acc[nt][j] = 0.0f;

    #pragma unroll
    for (int pass = 0; pass < 3; pass++) {
        const uint32_t aBase = sb + ((pass == 2) ? OFF_AL : OFF_AH) + aRel;
        const uint32_t bBase = sb + ((pass == 1) ? OFF_BL : OFF_BH) + bRelFix;
        #pragma unroll
        for (int kt = 0; kt < 8; kt++) {
            uint32_t a[4];
            ldsm_x4(a, aBase + kt * 32);
            #pragma unroll
            for (int nt = 0; nt < 8; nt++) {
                uint32_t b[2];
                ldsm_x2(b, bBase + nt * 8 * (KSTR * 2) + kt * 32);
                mma_bf16(acc[nt], a, b);
            }
        }
    }

    // ---- epilogue: write 64x128 partial tile ----
    float* part = &g_part[(size_t)blockIdx.x * (B_ * HG_)];
    const int qid = lane >> 2;        // 0..7
    const int tq  = lane & 3;         // 0..3
    const int row0 = mt * 16 + qid;
    #pragma unroll
    for (int nt = 0; nt < 8; nt++) {
        const int col = nh * 64 + nt * 8 + tq * 2;
        float2 v0; v0.x = acc[nt][0]; v0.y = acc[nt][1];
        float2 v1; v1.x = acc[nt][2]; v1.y = acc[nt][3];
        *reinterpret_cast<float2*>(part + row0 * HG_ + col) = v0;
        *reinterpret_cast<float2*>(part + (row0 + 8) * HG_ + col) = v1;
    }
}

// ---------------------------------------------------------------------------
// Kernel 3: reduce partials + bias + relu + l-branch (unchanged)
// ---------------------------------------------------------------------------
__global__ __launch_bounds__(512) void finalize_kernel(
    const float* __restrict__ l, const float* __restrict__ b1,
    const float* __restrict__ W2, const float* __restrict__ b2,
    float* __restrict__ out)
{
    __shared__ float red[4][HG_];
    const int b = blockIdx.x;
    const int tid = threadIdx.x;
    const int h = tid & 127;
    const int p = tid >> 7;

    float s = 0.0f;
    #pragma unroll 8
    for (int c = p; c < NCHUNK; c += 4)
        s += g_part[(size_t)c * (B_ * HG_) + b * HG_ + h];
    red[p][h] = s;
    __syncthreads();

    if (p == 0) {
        const float v = red[0][h] + red[1][h] + red[2][h] + red[3][h] + b1[h];
        out[b * (HG_ + HL_) + h] = fmaxf(v, 0.0f);
        const float lw = l[b * 2 + 0] * W2[h] + l[b * 2 + 1] * W2[HL_ + h] + b2[h];
        out[b * (HG_ + HL_) + HG_ + h] = fmaxf(lw, 0.0f);
    }
}

// ---------------------------------------------------------------------------
extern "C" void kernel_launch(void* const* d_in, const int* in_sizes, int n_in,
                              void* d_out, int out_size)
{
    const float* x  = (const float*)d_in[0];
    const float* l  = (const float*)d_in[1];
    const float* W1 = (const float*)d_in[2];
    const float* b1 = (const float*)d_in[3];
    const float* W2 = (const float*)d_in[4];
    const float* b2 = (const float*)d_in[5];
    float* out = (float*)d_out;

    static bool attr_set = false;
    if (!attr_set) {
        cudaFuncSetAttribute(gemm_mma_kernel,
                             cudaFuncAttributeMaxDynamicSharedMemorySize, SMEM_GEMM);
        attr_set = true;
    }

    dim3 eg(112, B_);
    extract_kernel<<<eg, 192>>>(x, l);
    gemm_mma_kernel<<<NCHUNK, 256, SMEM_GEMM>>>(W1);
    finalize_kernel<<<B_, 512>>>(l, b1, W2, b2, out);
}